// round 10
// baseline (speedup 1.0000x reference)
#include <cuda_runtime.h>
#include <cuda_bf16.h>
#include <cstdint>

#define NN 50000
#define BB 32
#define FF 200
#define EE 800000
#define NB (NN*BB)  // 1,600,000

#define FC1_BLOCKS 391   // ceil(NN/128) nodes, 128 nodes per 256-thr block
#define DEG_BLOCKS 782   // ceil(EE/1024), 4 edges per thread

// Scratch
__device__ float g_x[NB];      // fc1 output, node-major [n][b]
__device__ float g_s[NB];      // softmax denominator per (n,b)
__device__ float g_xenc[NB];   // elu(gat out)
__device__ float g_logits[BB*4];   // starts 0; k_final resets after reading
__device__ int   g_cnt[NN];        // starts 0; k_scan resets after reading
__device__ int   g_offs[NN+1]; // CSR offsets
__device__ int   g_rank[EE];   // rank of edge within its dst bucket
__device__ int   g_ssrc[EE];   // dst-sorted src indices

// ---------------------------------------------------------------- fused: fc1 (blocks [0,FC1_BLOCKS)) + degree histogram
__global__ void k_pre(const float* __restrict__ fd, const float* __restrict__ w,
                      const float* __restrict__ bias, const int* __restrict__ ei) {
    if (blockIdx.x < FC1_BLOCKS) {
        // ---- fc1: register-tiled 4 nodes x 4 batches / thread, no smem
        int lane = threadIdx.x & 31, warp = threadIdx.x >> 5;
        int nq = lane >> 3;
        int bq = lane & 7;
        int wbase = (blockIdx.x * 8 + warp) * 16;
        int n0 = wbase + nq;

        const float4* f0 = reinterpret_cast<const float4*>(fd + (size_t)(bq * 4 + 0) * FF);
        const float4* f1 = reinterpret_cast<const float4*>(fd + (size_t)(bq * 4 + 1) * FF);
        const float4* f2 = reinterpret_cast<const float4*>(fd + (size_t)(bq * 4 + 2) * FF);
        const float4* f3 = reinterpret_cast<const float4*>(fd + (size_t)(bq * 4 + 3) * FF);

        bool v0 = (n0      < NN), v1 = (n0 + 4  < NN),
             v2 = (n0 + 8  < NN), v3 = (n0 + 12 < NN);
        const float4* w0 = reinterpret_cast<const float4*>(w + (v0 ? (size_t)n0        * FF : 0));
        const float4* w1 = reinterpret_cast<const float4*>(w + (v1 ? (size_t)(n0 + 4)  * FF : 0));
        const float4* w2 = reinterpret_cast<const float4*>(w + (v2 ? (size_t)(n0 + 8)  * FF : 0));
        const float4* w3 = reinterpret_cast<const float4*>(w + (v3 ? (size_t)(n0 + 12) * FF : 0));

        float4 a0 = make_float4(0.f,0.f,0.f,0.f);
        float4 a1 = a0, a2 = a0, a3 = a0;

#pragma unroll 5
        for (int k4 = 0; k4 < FF / 4; ++k4) {
            float4 q0 = __ldg(f0 + k4), q1 = __ldg(f1 + k4),
                   q2 = __ldg(f2 + k4), q3 = __ldg(f3 + k4);
            float4 r0 = __ldg(w0 + k4), r1 = __ldg(w1 + k4),
                   r2 = __ldg(w2 + k4), r3 = __ldg(w3 + k4);
#define DOT4(wv, fv) (wv.x*fv.x + wv.y*fv.y + wv.z*fv.z + wv.w*fv.w)
            a0.x += DOT4(r0, q0); a0.y += DOT4(r0, q1); a0.z += DOT4(r0, q2); a0.w += DOT4(r0, q3);
            a1.x += DOT4(r1, q0); a1.y += DOT4(r1, q1); a1.z += DOT4(r1, q2); a1.w += DOT4(r1, q3);
            a2.x += DOT4(r2, q0); a2.y += DOT4(r2, q1); a2.z += DOT4(r2, q2); a2.w += DOT4(r2, q3);
            a3.x += DOT4(r3, q0); a3.y += DOT4(r3, q1); a3.z += DOT4(r3, q2); a3.w += DOT4(r3, q3);
#undef DOT4
        }
        float4* gx = reinterpret_cast<float4*>(g_x);
        if (v0) { float b = __ldg(bias + n0);
            a0.x += b; a0.y += b; a0.z += b; a0.w += b; gx[(size_t)n0 * 8 + bq] = a0; }
        if (v1) { float b = __ldg(bias + n0 + 4);
            a1.x += b; a1.y += b; a1.z += b; a1.w += b; gx[(size_t)(n0 + 4) * 8 + bq] = a1; }
        if (v2) { float b = __ldg(bias + n0 + 8);
            a2.x += b; a2.y += b; a2.z += b; a2.w += b; gx[(size_t)(n0 + 8) * 8 + bq] = a2; }
        if (v3) { float b = __ldg(bias + n0 + 12);
            a3.x += b; a3.y += b; a3.z += b; a3.w += b; gx[(size_t)(n0 + 12) * 8 + bq] = a3; }
    } else {
        // ---- degree histogram + per-edge rank, 4 edges/thread
        int e0 = ((blockIdx.x - FC1_BLOCKS) * 256 + threadIdx.x) * 4;
        if (e0 >= EE) return;
        int4 d4 = __ldg(reinterpret_cast<const int4*>(ei + EE) + (e0 >> 2));
        int r0 = atomicAdd(&g_cnt[d4.x], 1);
        int r1 = atomicAdd(&g_cnt[d4.y], 1);
        int r2 = atomicAdd(&g_cnt[d4.z], 1);
        int r3 = atomicAdd(&g_cnt[d4.w], 1);
        *reinterpret_cast<int4*>(g_rank + e0) = make_int4(r0, r1, r2, r3);
    }
}

// ---------------------------------------------------------------- exclusive scan (single block); re-zeroes g_cnt
__global__ void k_scan() {
    const int T = 1024;
    const int CH = (NN + T - 1) / T;  // 49
    int t = threadIdx.x;
    int base = t * CH;
    int cnt[CH];
    int sum = 0;
#pragma unroll
    for (int i = 0; i < CH; ++i) {
        int idx = base + i;
        cnt[i] = (idx < NN) ? g_cnt[idx] : 0;
        sum += cnt[i];
    }
    __shared__ int sh[T];
    sh[t] = sum;
    __syncthreads();
    for (int off = 1; off < T; off <<= 1) {
        int v = (t >= off) ? sh[t - off] : 0;
        __syncthreads();
        sh[t] += v;
        __syncthreads();
    }
    int run = sh[t] - sum;  // exclusive prefix of this chunk
#pragma unroll
    for (int i = 0; i < CH; ++i) {
        int idx = base + i;
        if (idx < NN) {
            g_offs[idx] = run;
            g_cnt[idx] = 0;          // restore invariant for next replay
            run += cnt[i];
        }
    }
    if (t == T - 1) g_offs[NN] = run;
}

// ---------------------------------------------------------------- scatter, 4 edges/thread, atomic-free
__global__ void k_scatter(const int* __restrict__ ei) {
    int e0 = (blockIdx.x * 256 + threadIdx.x) * 4;
    if (e0 >= EE) return;
    int4 s4 = __ldg(reinterpret_cast<const int4*>(ei) + (e0 >> 2));
    int4 d4 = __ldg(reinterpret_cast<const int4*>(ei + EE) + (e0 >> 2));
    int4 r4 = *reinterpret_cast<const int4*>(g_rank + e0);
    int o0 = g_offs[d4.x], o1 = g_offs[d4.y], o2 = g_offs[d4.z], o3 = g_offs[d4.w];
    g_ssrc[o0 + r4.x] = s4.x;
    g_ssrc[o1 + r4.y] = s4.y;
    g_ssrc[o2 + r4.z] = s4.z;
    g_ssrc[o3 + r4.w] = s4.w;
}

// ---------------------------------------------------------------- GAT pass: warp per dst node, lane = batch, MLP-16
__global__ void k_gat(const float* __restrict__ gatw, const float* __restrict__ asrc,
                      const float* __restrict__ adst, const float* __restrict__ gatb) {
    int n = blockIdx.x * 8 + (threadIdx.x >> 5);
    int lane = threadIdx.x & 31;
    float gw = __ldg(gatw);
    float p  = gw * __ldg(asrc);
    float q  = gw * __ldg(adst);

    float xd = g_x[n * 32 + lane];
    float qxd = q * xd;
    float ev = p * xd + qxd;
    ev = ev > 0.f ? ev : 0.2f * ev;
    float ex = __expf(ev);
    float s = ex, t = ex * xd;

    int beg = g_offs[n], end = g_offs[n + 1];
    int j = beg;
    for (; j + 16 <= end; j += 16) {
        int idx[16];
#pragma unroll
        for (int r = 0; r < 16; ++r) idx[r] = __ldg(g_ssrc + j + r);
        float xv[16];
#pragma unroll
        for (int r = 0; r < 16; ++r) xv[r] = g_x[idx[r] * 32 + lane];
#pragma unroll
        for (int r = 0; r < 16; ++r) {
            float e = fmaf(p, xv[r], qxd);
            e = e > 0.f ? e : 0.2f * e;
            e = __expf(e);
            s += e; t = fmaf(e, xv[r], t);
        }
    }
    for (; j + 4 <= end; j += 4) {
        int idx[4];
#pragma unroll
        for (int r = 0; r < 4; ++r) idx[r] = __ldg(g_ssrc + j + r);
        float xv[4];
#pragma unroll
        for (int r = 0; r < 4; ++r) xv[r] = g_x[idx[r] * 32 + lane];
#pragma unroll
        for (int r = 0; r < 4; ++r) {
            float e = fmaf(p, xv[r], qxd);
            e = e > 0.f ? e : 0.2f * e;
            e = __expf(e);
            s += e; t = fmaf(e, xv[r], t);
        }
    }
    for (; j < end; ++j) {
        float xs = g_x[__ldg(g_ssrc + j) * 32 + lane];
        float e = fmaf(p, xs, qxd);
        e = e > 0.f ? e : 0.2f * e;
        e = __expf(e);
        s += e; t = fmaf(e, xs, t);
    }

    g_s[n * 32 + lane] = s;
    float v = gw * t / s + __ldg(gatb);
    g_xenc[n * 32 + lane] = v > 0.f ? v : (__expf(v) - 1.f);
}

// ---------------------------------------------------------------- GCN pass + community epilogue + coalesced out
__global__ void k_gcn(const float* __restrict__ gatw, const float* __restrict__ asrc,
                      const float* __restrict__ adst,
                      const float* __restrict__ gcnw, const float* __restrict__ gcnb,
                      const float* __restrict__ lng, const float* __restrict__ lnb,
                      float* __restrict__ out) {
    __shared__ float sout[BB][25];
    int w = threadIdx.x >> 5;
    int n = blockIdx.x * 8 + w;
    int lane = threadIdx.x & 31;
    float gw = __ldg(gatw);
    float p  = gw * __ldg(asrc);
    float q  = gw * __ldg(adst);

    float xd = g_x[n * 32 + lane];
    float qxd = q * xd;
    float ev = p * xd + qxd;
    ev = ev > 0.f ? ev : 0.2f * ev;
    float ex = __expf(ev);
    float u = ex * g_xenc[n * 32 + lane];

    int beg = g_offs[n], end = g_offs[n + 1];
    int j = beg;
    for (; j + 16 <= end; j += 16) {
        int idx[16];
#pragma unroll
        for (int r = 0; r < 16; ++r) idx[r] = __ldg(g_ssrc + j + r);
        float xv[16], hv[16];
#pragma unroll
        for (int r = 0; r < 16; ++r) xv[r] = g_x[idx[r] * 32 + lane];
#pragma unroll
        for (int r = 0; r < 16; ++r) hv[r] = g_xenc[idx[r] * 32 + lane];
#pragma unroll
        for (int r = 0; r < 16; ++r) {
            float e = fmaf(p, xv[r], qxd);
            e = e > 0.f ? e : 0.2f * e;
            e = __expf(e);
            u = fmaf(e, hv[r], u);
        }
    }
    for (; j + 4 <= end; j += 4) {
        int idx[4];
#pragma unroll
        for (int r = 0; r < 4; ++r) idx[r] = __ldg(g_ssrc + j + r);
        float xv[4], hv[4];
#pragma unroll
        for (int r = 0; r < 4; ++r) xv[r] = g_x[idx[r] * 32 + lane];
#pragma unroll
        for (int r = 0; r < 4; ++r) hv[r] = g_xenc[idx[r] * 32 + lane];
#pragma unroll
        for (int r = 0; r < 4; ++r) {
            float e = fmaf(p, xv[r], qxd);
            e = e > 0.f ? e : 0.2f * e;
            e = __expf(e);
            u = fmaf(e, hv[r], u);
        }
    }
    for (; j < end; ++j) {
        int sj = __ldg(g_ssrc + j);
        float xs = g_x[sj * 32 + lane];
        float e = fmaf(p, xs, qxd);
        e = e > 0.f ? e : 0.2f * e;
        e = __expf(e);
        u = fmaf(e, g_xenc[sj * 32 + lane], u);
    }

    float y = u / g_s[n * 32 + lane];

    float c0 = y * __ldg(gcnw + 0) + __ldg(gcnb + 0);
    float c1 = y * __ldg(gcnw + 1) + __ldg(gcnb + 1);
    float c2 = y * __ldg(gcnw + 2) + __ldg(gcnb + 2);
    c0 = c0 > 0.f ? c0 : 0.01f * c0;
    c1 = c1 > 0.f ? c1 : 0.01f * c1;
    c2 = c2 > 0.f ? c2 : 0.01f * c2;
    float mu = (c0 + c1 + c2) * (1.f / 3.f);
    float d0 = c0 - mu, d1 = c1 - mu, d2 = c2 - mu;
    float var = (d0*d0 + d1*d1 + d2*d2) * (1.f / 3.f);
    float r = rsqrtf(var + 1e-5f);
    float v0 = d0 * r * __ldg(lng + 0) + __ldg(lnb + 0);
    float v1 = d1 * r * __ldg(lng + 1) + __ldg(lnb + 1);
    float v2 = d2 * r * __ldg(lng + 2) + __ldg(lnb + 2);
    float m = fmaxf(v0, fmaxf(v1, v2));
    float a0 = __expf(v0 - m), a1 = __expf(v1 - m), a2 = __expf(v2 - m);
    float inv = 1.f / (a0 + a1 + a2);

    sout[lane][w * 3 + 0] = a0 * inv;
    sout[lane][w * 3 + 1] = a1 * inv;
    sout[lane][w * 3 + 2] = a2 * inv;
    __syncthreads();

    int b = threadIdx.x >> 3, seg = threadIdx.x & 7;
    int n0 = blockIdx.x * 8;
    size_t base = 128 + ((size_t)b * NN + n0 + seg) * 3;
    out[base + 0] = sout[b][seg * 3 + 0];
    out[base + 1] = sout[b][seg * 3 + 1];
    out[base + 2] = sout[b][seg * 3 + 2];
}

// ---------------------------------------------------------------- classifier partial reduction
__global__ void k_logits(const float* __restrict__ clfw) {
    int wid = (blockIdx.x * blockDim.x + threadIdx.x) >> 5;
    int lane = threadIdx.x & 31;
    int W = (gridDim.x * blockDim.x) >> 5;
    float a0 = 0.f, a1 = 0.f, a2 = 0.f, a3 = 0.f;
    for (int n = wid; n < NN; n += W) {
        float v = g_xenc[n * 32 + lane];
        a0 = fmaf(v, __ldg(clfw + n),          a0);
        a1 = fmaf(v, __ldg(clfw + NN + n),     a1);
        a2 = fmaf(v, __ldg(clfw + 2 * NN + n), a2);
        a3 = fmaf(v, __ldg(clfw + 3 * NN + n), a3);
    }
    atomicAdd(&g_logits[lane * 4 + 0], a0);
    atomicAdd(&g_logits[lane * 4 + 1], a1);
    atomicAdd(&g_logits[lane * 4 + 2], a2);
    atomicAdd(&g_logits[lane * 4 + 3], a3);
}

// ---------------------------------------------------------------- final softmax; resets g_logits for next replay
__global__ void k_final(const float* __restrict__ clfb, float* __restrict__ out) {
    int b = threadIdx.x;
    if (b >= BB) return;
    float l0 = g_logits[b * 4 + 0] + __ldg(clfb + 0);
    float l1 = g_logits[b * 4 + 1] + __ldg(clfb + 1);
    float l2 = g_logits[b * 4 + 2] + __ldg(clfb + 2);
    float l3 = g_logits[b * 4 + 3] + __ldg(clfb + 3);
    g_logits[b * 4 + 0] = 0.f;
    g_logits[b * 4 + 1] = 0.f;
    g_logits[b * 4 + 2] = 0.f;
    g_logits[b * 4 + 3] = 0.f;
    float m = fmaxf(fmaxf(l0, l1), fmaxf(l2, l3));
    float e0 = __expf(l0 - m), e1 = __expf(l1 - m), e2 = __expf(l2 - m), e3 = __expf(l3 - m);
    float inv = 1.f / (e0 + e1 + e2 + e3);
    out[b * 4 + 0] = e0 * inv;
    out[b * 4 + 1] = e1 * inv;
    out[b * 4 + 2] = e2 * inv;
    out[b * 4 + 3] = e3 * inv;
}

extern "C" void kernel_launch(void* const* d_in, const int* in_sizes, int n_in,
                              void* d_out, int out_size) {
    const float* fd    = (const float*)d_in[0];
    const float* fc1w  = (const float*)d_in[1];
    const float* fc1b  = (const float*)d_in[2];
    const float* gatw  = (const float*)d_in[3];
    const float* asrc  = (const float*)d_in[4];
    const float* adst  = (const float*)d_in[5];
    const float* gatb  = (const float*)d_in[6];
    const float* gcnw  = (const float*)d_in[7];
    const float* gcnb  = (const float*)d_in[8];
    const float* lng   = (const float*)d_in[9];
    const float* lnb   = (const float*)d_in[10];
    const float* clfw  = (const float*)d_in[11];
    const float* clfb  = (const float*)d_in[12];
    const int*   ei    = (const int*)d_in[13];
    float* out = (float*)d_out;

    k_pre<<<FC1_BLOCKS + DEG_BLOCKS, 256>>>(fd, fc1w, fc1b, ei);
    k_scan<<<1, 1024>>>();
    k_scatter<<<DEG_BLOCKS, 256>>>(ei);
    k_gat<<<NN / 8, 256>>>(gatw, asrc, adst, gatb);
    k_gcn<<<NN / 8, 256>>>(gatw, asrc, adst, gcnw, gcnb, lng, lnb, out);
    k_logits<<<128, 256>>>(clfw);
    k_final<<<1, 32>>>(clfb, out);
}

// round 13
// speedup vs baseline: 1.4210x; 1.4210x over previous
#include <cuda_runtime.h>
#include <cuda_bf16.h>
#include <cstdint>

#define NN 50000
#define BB 32
#define FF 200
#define EE 800000
#define NB (NN*BB)  // 1,600,000

#define FC1_BLOCKS 391     // ceil(NN/128) nodes, 128 nodes per 256-thr block
#define DEG_BLOCKS 782     // ceil(EE/1024), 4 edges per thread
#define SCAT_BLOCKS 391    // ceil(EE/2048), 8 edges per thread
#define SCAN_BLOCKS 196    // ceil(NN/256)
#define GCN_BLOCKS 6250    // NN/8
#define LOG_BLOCKS 128

// Scratch
__device__ float g_x[NB];      // fc1 output, node-major [n][b]
__device__ float g_s[NB];      // softmax denominator per (n,b)
__device__ float g_xenc[NB];   // elu(gat out)
__device__ float g_logits[BB*4];   // starts 0; k_final resets after reading
__device__ int   g_cnt[NN];        // starts 0; k_scanB resets after reading
__device__ int   g_bsum[SCAN_BLOCKS];
__device__ int   g_offs[NN+1]; // CSR offsets
__device__ int   g_rank[EE];   // rank of edge within its dst bucket
__device__ int   g_ssrc[EE];   // dst-sorted src indices

// ---------------------------------------------------------------- fused: fc1 (blocks [0,FC1_BLOCKS)) + degree histogram
__global__ void k_pre(const float* __restrict__ fd, const float* __restrict__ w,
                      const float* __restrict__ bias, const int* __restrict__ ei) {
    if (blockIdx.x < FC1_BLOCKS) {
        // ---- fc1: register-tiled 4 nodes x 4 batches / thread, no smem
        int lane = threadIdx.x & 31, warp = threadIdx.x >> 5;
        int nq = lane >> 3;
        int bq = lane & 7;
        int wbase = (blockIdx.x * 8 + warp) * 16;
        int n0 = wbase + nq;

        const float4* f0 = reinterpret_cast<const float4*>(fd + (size_t)(bq * 4 + 0) * FF);
        const float4* f1 = reinterpret_cast<const float4*>(fd + (size_t)(bq * 4 + 1) * FF);
        const float4* f2 = reinterpret_cast<const float4*>(fd + (size_t)(bq * 4 + 2) * FF);
        const float4* f3 = reinterpret_cast<const float4*>(fd + (size_t)(bq * 4 + 3) * FF);

        bool v0 = (n0      < NN), v1 = (n0 + 4  < NN),
             v2 = (n0 + 8  < NN), v3 = (n0 + 12 < NN);
        const float4* w0 = reinterpret_cast<const float4*>(w + (v0 ? (size_t)n0        * FF : 0));
        const float4* w1 = reinterpret_cast<const float4*>(w + (v1 ? (size_t)(n0 + 4)  * FF : 0));
        const float4* w2 = reinterpret_cast<const float4*>(w + (v2 ? (size_t)(n0 + 8)  * FF : 0));
        const float4* w3 = reinterpret_cast<const float4*>(w + (v3 ? (size_t)(n0 + 12) * FF : 0));

        float4 a0 = make_float4(0.f,0.f,0.f,0.f);
        float4 a1 = a0, a2 = a0, a3 = a0;

#pragma unroll 5
        for (int k4 = 0; k4 < FF / 4; ++k4) {
            float4 q0 = __ldg(f0 + k4), q1 = __ldg(f1 + k4),
                   q2 = __ldg(f2 + k4), q3 = __ldg(f3 + k4);
            float4 r0 = __ldg(w0 + k4), r1 = __ldg(w1 + k4),
                   r2 = __ldg(w2 + k4), r3 = __ldg(w3 + k4);
#define DOT4(wv, fv) (wv.x*fv.x + wv.y*fv.y + wv.z*fv.z + wv.w*fv.w)
            a0.x += DOT4(r0, q0); a0.y += DOT4(r0, q1); a0.z += DOT4(r0, q2); a0.w += DOT4(r0, q3);
            a1.x += DOT4(r1, q0); a1.y += DOT4(r1, q1); a1.z += DOT4(r1, q2); a1.w += DOT4(r1, q3);
            a2.x += DOT4(r2, q0); a2.y += DOT4(r2, q1); a2.z += DOT4(r2, q2); a2.w += DOT4(r2, q3);
            a3.x += DOT4(r3, q0); a3.y += DOT4(r3, q1); a3.z += DOT4(r3, q2); a3.w += DOT4(r3, q3);
#undef DOT4
        }
        float4* gx = reinterpret_cast<float4*>(g_x);
        if (v0) { float b = __ldg(bias + n0);
            a0.x += b; a0.y += b; a0.z += b; a0.w += b; gx[(size_t)n0 * 8 + bq] = a0; }
        if (v1) { float b = __ldg(bias + n0 + 4);
            a1.x += b; a1.y += b; a1.z += b; a1.w += b; gx[(size_t)(n0 + 4) * 8 + bq] = a1; }
        if (v2) { float b = __ldg(bias + n0 + 8);
            a2.x += b; a2.y += b; a2.z += b; a2.w += b; gx[(size_t)(n0 + 8) * 8 + bq] = a2; }
        if (v3) { float b = __ldg(bias + n0 + 12);
            a3.x += b; a3.y += b; a3.z += b; a3.w += b; gx[(size_t)(n0 + 12) * 8 + bq] = a3; }
    } else {
        // ---- degree histogram + per-edge rank, 4 edges/thread
        int e0 = ((blockIdx.x - FC1_BLOCKS) * 256 + threadIdx.x) * 4;
        if (e0 >= EE) return;
        int4 d4 = __ldg(reinterpret_cast<const int4*>(ei + EE) + (e0 >> 2));
        int r0 = atomicAdd(&g_cnt[d4.x], 1);
        int r1 = atomicAdd(&g_cnt[d4.y], 1);
        int r2 = atomicAdd(&g_cnt[d4.z], 1);
        int r3 = atomicAdd(&g_cnt[d4.w], 1);
        *reinterpret_cast<int4*>(g_rank + e0) = make_int4(r0, r1, r2, r3);
    }
}

// ---------------------------------------------------------------- scan phase A: per-block degree sums
__global__ void k_scanA() {
    __shared__ int sh[256];
    int t = threadIdx.x;
    int i = blockIdx.x * 256 + t;
    sh[t] = (i < NN) ? g_cnt[i] : 0;
    __syncthreads();
#pragma unroll
    for (int off = 128; off > 0; off >>= 1) {
        if (t < off) sh[t] += sh[t + off];
        __syncthreads();
    }
    if (t == 0) {
        g_bsum[blockIdx.x] = sh[0];
        if (blockIdx.x == 0) g_offs[NN] = EE;
    }
}

// ---------------------------------------------------------------- scan phase B: offsets (each block scans bsums + own 256)
__global__ void k_scanB() {
    __shared__ int sb[256];
    __shared__ int s2[256];
    int t = threadIdx.x;

    // inclusive scan of the 196 block sums (same computation in every block)
    sb[t] = (t < SCAN_BLOCKS) ? g_bsum[t] : 0;
    __syncthreads();
#pragma unroll
    for (int off = 1; off < 256; off <<= 1) {
        int tmp = (t >= off) ? sb[t - off] : 0;
        __syncthreads();
        sb[t] += tmp;
        __syncthreads();
    }
    int boff = (blockIdx.x == 0) ? 0 : sb[blockIdx.x - 1];

    // block-local exclusive scan of this block's 256 counts
    int i = blockIdx.x * 256 + t;
    int c = (i < NN) ? g_cnt[i] : 0;
    s2[t] = c;
    __syncthreads();
#pragma unroll
    for (int off = 1; off < 256; off <<= 1) {
        int tmp = (t >= off) ? s2[t - off] : 0;
        __syncthreads();
        s2[t] += tmp;
        __syncthreads();
    }
    if (i < NN) {
        g_offs[i] = boff + (s2[t] - c);
        g_cnt[i] = 0;   // restore invariant for next graph replay
    }
}

// ---------------------------------------------------------------- scatter, 8 edges/thread, atomic-free
__global__ void k_scatter(const int* __restrict__ ei) {
    int e0 = (blockIdx.x * 256 + threadIdx.x) * 8;
    if (e0 >= EE) return;
    int4 sA = __ldg(reinterpret_cast<const int4*>(ei) + (e0 >> 2));
    int4 sB = __ldg(reinterpret_cast<const int4*>(ei) + (e0 >> 2) + 1);
    int4 dA = __ldg(reinterpret_cast<const int4*>(ei + EE) + (e0 >> 2));
    int4 dB = __ldg(reinterpret_cast<const int4*>(ei + EE) + (e0 >> 2) + 1);
    int4 rA = *reinterpret_cast<const int4*>(g_rank + e0);
    int4 rB = *reinterpret_cast<const int4*>(g_rank + e0 + 4);
    int o0 = g_offs[dA.x], o1 = g_offs[dA.y], o2 = g_offs[dA.z], o3 = g_offs[dA.w];
    int o4 = g_offs[dB.x], o5 = g_offs[dB.y], o6 = g_offs[dB.z], o7 = g_offs[dB.w];
    g_ssrc[o0 + rA.x] = sA.x;
    g_ssrc[o1 + rA.y] = sA.y;
    g_ssrc[o2 + rA.z] = sA.z;
    g_ssrc[o3 + rA.w] = sA.w;
    g_ssrc[o4 + rB.x] = sB.x;
    g_ssrc[o5 + rB.y] = sB.y;
    g_ssrc[o6 + rB.z] = sB.z;
    g_ssrc[o7 + rB.w] = sB.w;
}

// ---------------------------------------------------------------- GAT pass: warp per dst node, lane = batch
__global__ void k_gat(const float* __restrict__ gatw, const float* __restrict__ asrc,
                      const float* __restrict__ adst, const float* __restrict__ gatb) {
    int n = blockIdx.x * 8 + (threadIdx.x >> 5);
    int lane = threadIdx.x & 31;
    float gw = __ldg(gatw);
    float p  = gw * __ldg(asrc);
    float q  = gw * __ldg(adst);

    float xd = g_x[n * 32 + lane];
    float qxd = q * xd;
    float ev = p * xd + qxd;
    ev = ev > 0.f ? ev : 0.2f * ev;
    float ex = __expf(ev);
    float s = ex, t = ex * xd;

    int beg = g_offs[n], end = g_offs[n + 1];
    int j = beg;
    for (; j + 8 <= end; j += 8) {
        int idx[8];
#pragma unroll
        for (int r = 0; r < 8; ++r) idx[r] = __ldg(g_ssrc + j + r);
        float xv[8];
#pragma unroll
        for (int r = 0; r < 8; ++r) xv[r] = g_x[idx[r] * 32 + lane];
#pragma unroll
        for (int r = 0; r < 8; ++r) {
            float e = fmaf(p, xv[r], qxd);
            e = e > 0.f ? e : 0.2f * e;
            e = __expf(e);
            s += e; t = fmaf(e, xv[r], t);
        }
    }
    for (; j < end; ++j) {
        float xs = g_x[__ldg(g_ssrc + j) * 32 + lane];
        float e = fmaf(p, xs, qxd);
        e = e > 0.f ? e : 0.2f * e;
        e = __expf(e);
        s += e; t = fmaf(e, xs, t);
    }

    g_s[n * 32 + lane] = s;
    float v = gw * t / s + __ldg(gatb);
    g_xenc[n * 32 + lane] = v > 0.f ? v : (__expf(v) - 1.f);
}

// ---------------------------------------------------------------- fused: classifier logits (blocks [0,LOG)) + GCN pass
__global__ void k_gcnlog(const float* __restrict__ gatw, const float* __restrict__ asrc,
                         const float* __restrict__ adst,
                         const float* __restrict__ gcnw, const float* __restrict__ gcnb,
                         const float* __restrict__ lng, const float* __restrict__ lnb,
                         const float* __restrict__ clfw,
                         float* __restrict__ out) {
    if (blockIdx.x < LOG_BLOCKS) {
        // ---- classifier partial reduction
        int wid = (blockIdx.x * 256 + threadIdx.x) >> 5;
        int lane = threadIdx.x & 31;
        const int W = LOG_BLOCKS * 8;
        float a0 = 0.f, a1 = 0.f, a2 = 0.f, a3 = 0.f;
        for (int n = wid; n < NN; n += W) {
            float v = g_xenc[n * 32 + lane];
            a0 = fmaf(v, __ldg(clfw + n),          a0);
            a1 = fmaf(v, __ldg(clfw + NN + n),     a1);
            a2 = fmaf(v, __ldg(clfw + 2 * NN + n), a2);
            a3 = fmaf(v, __ldg(clfw + 3 * NN + n), a3);
        }
        atomicAdd(&g_logits[lane * 4 + 0], a0);
        atomicAdd(&g_logits[lane * 4 + 1], a1);
        atomicAdd(&g_logits[lane * 4 + 2], a2);
        atomicAdd(&g_logits[lane * 4 + 3], a3);
        return;
    }

    // ---- GCN pass + community epilogue + coalesced out
    __shared__ float sout[BB][25];
    int blk = blockIdx.x - LOG_BLOCKS;
    int w = threadIdx.x >> 5;
    int n = blk * 8 + w;
    int lane = threadIdx.x & 31;
    float gw = __ldg(gatw);
    float p  = gw * __ldg(asrc);
    float q  = gw * __ldg(adst);

    float xd = g_x[n * 32 + lane];
    float qxd = q * xd;
    float ev = p * xd + qxd;
    ev = ev > 0.f ? ev : 0.2f * ev;
    float ex = __expf(ev);
    float u = ex * g_xenc[n * 32 + lane];

    int beg = g_offs[n], end = g_offs[n + 1];
    int j = beg;
    for (; j + 8 <= end; j += 8) {
        int idx[8];
#pragma unroll
        for (int r = 0; r < 8; ++r) idx[r] = __ldg(g_ssrc + j + r);
        float xv[8], hv[8];
#pragma unroll
        for (int r = 0; r < 8; ++r) xv[r] = g_x[idx[r] * 32 + lane];
#pragma unroll
        for (int r = 0; r < 8; ++r) hv[r] = g_xenc[idx[r] * 32 + lane];
#pragma unroll
        for (int r = 0; r < 8; ++r) {
            float e = fmaf(p, xv[r], qxd);
            e = e > 0.f ? e : 0.2f * e;
            e = __expf(e);
            u = fmaf(e, hv[r], u);
        }
    }
    for (; j < end; ++j) {
        int sj = __ldg(g_ssrc + j);
        float xs = g_x[sj * 32 + lane];
        float e = fmaf(p, xs, qxd);
        e = e > 0.f ? e : 0.2f * e;
        e = __expf(e);
        u = fmaf(e, g_xenc[sj * 32 + lane], u);
    }

    float y = u / g_s[n * 32 + lane];   // weighted degree == 1 -> norm == alpha

    float c0 = y * __ldg(gcnw + 0) + __ldg(gcnb + 0);
    float c1 = y * __ldg(gcnw + 1) + __ldg(gcnb + 1);
    float c2 = y * __ldg(gcnw + 2) + __ldg(gcnb + 2);
    c0 = c0 > 0.f ? c0 : 0.01f * c0;
    c1 = c1 > 0.f ? c1 : 0.01f * c1;
    c2 = c2 > 0.f ? c2 : 0.01f * c2;
    float mu = (c0 + c1 + c2) * (1.f / 3.f);
    float d0 = c0 - mu, d1 = c1 - mu, d2 = c2 - mu;
    float var = (d0*d0 + d1*d1 + d2*d2) * (1.f / 3.f);
    float r = rsqrtf(var + 1e-5f);
    float v0 = d0 * r * __ldg(lng + 0) + __ldg(lnb + 0);
    float v1 = d1 * r * __ldg(lng + 1) + __ldg(lnb + 1);
    float v2 = d2 * r * __ldg(lng + 2) + __ldg(lnb + 2);
    float m = fmaxf(v0, fmaxf(v1, v2));
    float a0 = __expf(v0 - m), a1 = __expf(v1 - m), a2 = __expf(v2 - m);
    float inv = 1.f / (a0 + a1 + a2);

    sout[lane][w * 3 + 0] = a0 * inv;
    sout[lane][w * 3 + 1] = a1 * inv;
    sout[lane][w * 3 + 2] = a2 * inv;
    __syncthreads();

    int b = threadIdx.x >> 3, seg = threadIdx.x & 7;
    int n0 = blk * 8;
    size_t base = 128 + ((size_t)b * NN + n0 + seg) * 3;
    out[base + 0] = sout[b][seg * 3 + 0];
    out[base + 1] = sout[b][seg * 3 + 1];
    out[base + 2] = sout[b][seg * 3 + 2];
}

// ---------------------------------------------------------------- final softmax; resets g_logits for next replay
__global__ void k_final(const float* __restrict__ clfb, float* __restrict__ out) {
    int b = threadIdx.x;
    if (b >= BB) return;
    float l0 = g_logits[b * 4 + 0] + __ldg(clfb + 0);
    float l1 = g_logits[b * 4 + 1] + __ldg(clfb + 1);
    float l2 = g_logits[b * 4 + 2] + __ldg(clfb + 2);
    float l3 = g_logits[b * 4 + 3] + __ldg(clfb + 3);
    g_logits[b * 4 + 0] = 0.f;
    g_logits[b * 4 + 1] = 0.f;
    g_logits[b * 4 + 2] = 0.f;
    g_logits[b * 4 + 3] = 0.f;
    float m = fmaxf(fmaxf(l0, l1), fmaxf(l2, l3));
    float e0 = __expf(l0 - m), e1 = __expf(l1 - m), e2 = __expf(l2 - m), e3 = __expf(l3 - m);
    float inv = 1.f / (e0 + e1 + e2 + e3);
    out[b * 4 + 0] = e0 * inv;
    out[b * 4 + 1] = e1 * inv;
    out[b * 4 + 2] = e2 * inv;
    out[b * 4 + 3] = e3 * inv;
}

extern "C" void kernel_launch(void* const* d_in, const int* in_sizes, int n_in,
                              void* d_out, int out_size) {
    const float* fd    = (const float*)d_in[0];
    const float* fc1w  = (const float*)d_in[1];
    const float* fc1b  = (const float*)d_in[2];
    const float* gatw  = (const float*)d_in[3];
    const float* asrc  = (const float*)d_in[4];
    const float* adst  = (const float*)d_in[5];
    const float* gatb  = (const float*)d_in[6];
    const float* gcnw  = (const float*)d_in[7];
    const float* gcnb  = (const float*)d_in[8];
    const float* lng   = (const float*)d_in[9];
    const float* lnb   = (const float*)d_in[10];
    const float* clfw  = (const float*)d_in[11];
    const float* clfb  = (const float*)d_in[12];
    const int*   ei    = (const int*)d_in[13];
    float* out = (float*)d_out;

    k_pre<<<FC1_BLOCKS + DEG_BLOCKS, 256>>>(fd, fc1w, fc1b, ei);
    k_scanA<<<SCAN_BLOCKS, 256>>>();
    k_scanB<<<SCAN_BLOCKS, 256>>>();
    k_scatter<<<SCAT_BLOCKS, 256>>>(ei);
    k_gat<<<NN / 8, 256>>>(gatw, asrc, adst, gatb);
    k_gcnlog<<<LOG_BLOCKS + GCN_BLOCKS, 256>>>(gatw, asrc, adst, gcnw, gcnb, lng, lnb, clfw, out);
    k_final<<<1, 32>>>(clfb, out);
}

// round 14
// speedup vs baseline: 1.8426x; 1.2966x over previous
#include <cuda_runtime.h>
#include <cuda_bf16.h>
#include <cstdint>

#define NN 50000
#define BB 32
#define FF 200
#define EE 800000
#define NB (NN*BB)  // 1,600,000

#define FC1_BLOCKS 391     // 128 nodes per 256-thr block
#define DEG_BLOCKS 782     // ceil(EE/1024), 4 edges per thread
#define SCAT_BLOCKS 391    // ceil(EE/2048), 8 edges per thread
#define SCAN_BLOCKS 196    // ceil(NN/256)
#define GCN_BLOCKS 6250    // NN/8

// Scratch
__device__ float g_x[NB];      // fc1 output, node-major [n][b]
__device__ float g_s[NB];      // softmax denominator per (n,b)
__device__ float g_xenc[NB];   // elu(gat out)
__device__ float g_logits[BB*4];   // starts 0; k_final resets after reading
__device__ int   g_cnt[NN];        // starts 0; k_scan resets after reading
__device__ int   g_bsum[SCAN_BLOCKS];
__device__ int   g_offs[NN+1]; // CSR offsets
__device__ int   g_rank[EE];   // rank of edge within its dst bucket
__device__ int   g_ssrc[EE];   // dst-sorted src indices
__device__ int   g_flagA;      // scan barrier (self-resetting)
__device__ int   g_flagB;

typedef unsigned long long ull;

#define PACK2(dst, s) asm("mov.b64 %0, {%1, %1};" : "=l"(dst) : "f"(s))
#define FMA2(acc, a, b) asm("fma.rn.f32x2 %0, %1, %2, %0;" : "+l"(acc) : "l"(a), "l"(b))
#define UNPACK2(lo, hi, v) asm("mov.b64 {%0, %1}, %2;" : "=f"(lo), "=f"(hi) : "l"(v))

// ---------------------------------------------------------------- fused: fc1 (f32x2) + degree histogram
__global__ void k_pre(const float* __restrict__ fd, const float* __restrict__ w,
                      const float* __restrict__ bias, const int* __restrict__ ei) {
    if (blockIdx.x < FC1_BLOCKS) {
        // ---- fc1: 2 nodes x 8 batches per thread, packed f32x2 FMA
        __shared__ __align__(16) float fdT[FF * BB];  // [k][b], 25.6KB
        int tid = threadIdx.x;
        for (int i = tid; i < FF * BB; i += 256) {
            int b = i / FF, k = i % FF;
            fdT[k * BB + b] = fd[i];
        }
        __syncthreads();

        int lane = tid & 31, warp = tid >> 5;
        int nq = lane >> 2;       // 0..7
        int bq = lane & 3;        // 0..3 -> batches 8bq..8bq+7
        int node0 = (blockIdx.x * 8 + warp) * 16 + nq * 2;
        bool v0 = (node0 < NN), v1 = (node0 + 1 < NN);
        const float4* w0 = reinterpret_cast<const float4*>(w + (v0 ? (size_t)node0 * FF : 0));
        const float4* w1 = reinterpret_cast<const float4*>(w + (v1 ? (size_t)(node0 + 1) * FF : 0));

        ull acc0[4] = {0ull, 0ull, 0ull, 0ull};   // node0: 4 batch-pairs
        ull acc1[4] = {0ull, 0ull, 0ull, 0ull};   // node0+1

        const ull* fbase = reinterpret_cast<const ull*>(fdT) + bq * 4;  // 8 floats = 4 pairs

#pragma unroll 5
        for (int k4 = 0; k4 < FF / 4; ++k4) {
            float4 wa = __ldg(w0 + k4);
            float4 wb = __ldg(w1 + k4);
            float was[4] = {wa.x, wa.y, wa.z, wa.w};
            float wbs[4] = {wb.x, wb.y, wb.z, wb.w};
#pragma unroll
            for (int kk = 0; kk < 4; ++kk) {
                const ull* fp = fbase + (k4 * 4 + kk) * (BB / 2);
                ull f0 = fp[0], f1 = fp[1], f2 = fp[2], f3 = fp[3];
                ull wwa, wwb;
                PACK2(wwa, was[kk]);
                PACK2(wwb, wbs[kk]);
                FMA2(acc0[0], wwa, f0); FMA2(acc0[1], wwa, f1);
                FMA2(acc0[2], wwa, f2); FMA2(acc0[3], wwa, f3);
                FMA2(acc1[0], wwb, f0); FMA2(acc1[1], wwb, f1);
                FMA2(acc1[2], wwb, f2); FMA2(acc1[3], wwb, f3);
            }
        }

        if (v0) {
            float b = __ldg(bias + node0);
            float l0,h0,l1,h1,l2,h2,l3,h3;
            UNPACK2(l0,h0,acc0[0]); UNPACK2(l1,h1,acc0[1]);
            UNPACK2(l2,h2,acc0[2]); UNPACK2(l3,h3,acc0[3]);
            float4* gx = reinterpret_cast<float4*>(g_x + (size_t)node0 * 32 + bq * 8);
            gx[0] = make_float4(l0+b, h0+b, l1+b, h1+b);
            gx[1] = make_float4(l2+b, h2+b, l3+b, h3+b);
        }
        if (v1) {
            float b = __ldg(bias + node0 + 1);
            float l0,h0,l1,h1,l2,h2,l3,h3;
            UNPACK2(l0,h0,acc1[0]); UNPACK2(l1,h1,acc1[1]);
            UNPACK2(l2,h2,acc1[2]); UNPACK2(l3,h3,acc1[3]);
            float4* gx = reinterpret_cast<float4*>(g_x + (size_t)(node0 + 1) * 32 + bq * 8);
            gx[0] = make_float4(l0+b, h0+b, l1+b, h1+b);
            gx[1] = make_float4(l2+b, h2+b, l3+b, h3+b);
        }
    } else {
        // ---- degree histogram + per-edge rank, 4 edges/thread
        int e0 = ((blockIdx.x - FC1_BLOCKS) * 256 + threadIdx.x) * 4;
        if (e0 >= EE) return;
        int4 d4 = __ldg(reinterpret_cast<const int4*>(ei + EE) + (e0 >> 2));
        int r0 = atomicAdd(&g_cnt[d4.x], 1);
        int r1 = atomicAdd(&g_cnt[d4.y], 1);
        int r2 = atomicAdd(&g_cnt[d4.z], 1);
        int r3 = atomicAdd(&g_cnt[d4.w], 1);
        *reinterpret_cast<int4*>(g_rank + e0) = make_int4(r0, r1, r2, r3);
    }
}

// ---------------------------------------------------------------- fused scan: local scan + soft grid barrier + offsets
__global__ void k_scan() {
    __shared__ int s2[256];
    __shared__ int sb[256];
    int t = threadIdx.x;
    int i = blockIdx.x * 256 + t;
    int c = (i < NN) ? g_cnt[i] : 0;

    // block-local inclusive scan
    s2[t] = c;
    __syncthreads();
#pragma unroll
    for (int off = 1; off < 256; off <<= 1) {
        int tmp = (t >= off) ? s2[t - off] : 0;
        __syncthreads();
        s2[t] += tmp;
        __syncthreads();
    }
    if (t == 255) {
        g_bsum[blockIdx.x] = s2[255];
        __threadfence();
        atomicAdd(&g_flagA, 1);
    }
    // soft grid barrier (all 196 blocks co-resident: 196 << capacity)
    if (t == 0) {
        while (*((volatile int*)&g_flagA) < SCAN_BLOCKS) { __nanosleep(64); }
    }
    __syncthreads();

    // scan of block sums (each block computes the same prefix)
    sb[t] = (t < SCAN_BLOCKS) ? *((volatile int*)&g_bsum[t]) : 0;
    __syncthreads();
#pragma unroll
    for (int off = 1; off < 256; off <<= 1) {
        int tmp = (t >= off) ? sb[t - off] : 0;
        __syncthreads();
        sb[t] += tmp;
        __syncthreads();
    }
    int boff = (blockIdx.x == 0) ? 0 : sb[blockIdx.x - 1];

    if (i < NN) {
        g_offs[i] = boff + (s2[t] - c);   // exclusive
        g_cnt[i] = 0;                      // restore invariant for next replay
    }
    if (blockIdx.x == 0 && t == 0) g_offs[NN] = EE;

    // reset barrier flags for next graph replay (safe: B only increments after A-barrier passage)
    __syncthreads();
    if (t == 0) {
        int v = atomicAdd(&g_flagB, 1);
        if (v == SCAN_BLOCKS - 1) { g_flagA = 0; g_flagB = 0; __threadfence(); }
    }
}

// ---------------------------------------------------------------- scatter, 8 edges/thread, atomic-free
__global__ void k_scatter(const int* __restrict__ ei) {
    int e0 = (blockIdx.x * 256 + threadIdx.x) * 8;
    if (e0 >= EE) return;
    int4 sA = __ldg(reinterpret_cast<const int4*>(ei) + (e0 >> 2));
    int4 sB = __ldg(reinterpret_cast<const int4*>(ei) + (e0 >> 2) + 1);
    int4 dA = __ldg(reinterpret_cast<const int4*>(ei + EE) + (e0 >> 2));
    int4 dB = __ldg(reinterpret_cast<const int4*>(ei + EE) + (e0 >> 2) + 1);
    int4 rA = *reinterpret_cast<const int4*>(g_rank + e0);
    int4 rB = *reinterpret_cast<const int4*>(g_rank + e0 + 4);
    int o0 = g_offs[dA.x], o1 = g_offs[dA.y], o2 = g_offs[dA.z], o3 = g_offs[dA.w];
    int o4 = g_offs[dB.x], o5 = g_offs[dB.y], o6 = g_offs[dB.z], o7 = g_offs[dB.w];
    g_ssrc[o0 + rA.x] = sA.x;
    g_ssrc[o1 + rA.y] = sA.y;
    g_ssrc[o2 + rA.z] = sA.z;
    g_ssrc[o3 + rA.w] = sA.w;
    g_ssrc[o4 + rB.x] = sB.x;
    g_ssrc[o5 + rB.y] = sB.y;
    g_ssrc[o6 + rB.z] = sB.z;
    g_ssrc[o7 + rB.w] = sB.w;
}

// ---------------------------------------------------------------- GAT pass + fused classifier logits
__global__ void k_gat(const float* __restrict__ gatw, const float* __restrict__ asrc,
                      const float* __restrict__ adst, const float* __restrict__ gatb,
                      const float* __restrict__ clfw) {
    __shared__ float slog[BB * 4];
    int w8 = threadIdx.x >> 5;
    int n = blockIdx.x * 8 + w8;
    int lane = threadIdx.x & 31;
    if (threadIdx.x < BB * 4) slog[threadIdx.x] = 0.f;
    __syncthreads();

    float gw = __ldg(gatw);
    float p  = gw * __ldg(asrc);
    float q  = gw * __ldg(adst);

    float xd = g_x[n * 32 + lane];
    float qxd = q * xd;
    float ev = p * xd + qxd;
    ev = fmaxf(ev, 0.2f * ev);
    float ex = __expf(ev);
    float s = ex, t = ex * xd;

    int beg = g_offs[n], end = g_offs[n + 1];
    int j = beg;
    // align to 4
    for (; j < end && (j & 3); ++j) {
        float xs = g_x[__ldg(g_ssrc + j) * 32 + lane];
        float e = fmaf(p, xs, qxd); e = fmaxf(e, 0.2f * e); e = __expf(e);
        s += e; t = fmaf(e, xs, t);
    }
    for (; j + 8 <= end; j += 8) {
        int4 iA = *reinterpret_cast<const int4*>(g_ssrc + j);
        int4 iB = *reinterpret_cast<const int4*>(g_ssrc + j + 4);
        int idx[8] = {iA.x, iA.y, iA.z, iA.w, iB.x, iB.y, iB.z, iB.w};
        float xv[8];
#pragma unroll
        for (int r = 0; r < 8; ++r) xv[r] = g_x[idx[r] * 32 + lane];
#pragma unroll
        for (int r = 0; r < 8; ++r) {
            float e = fmaf(p, xv[r], qxd);
            e = fmaxf(e, 0.2f * e);
            e = __expf(e);
            s += e; t = fmaf(e, xv[r], t);
        }
    }
    for (; j < end; ++j) {
        float xs = g_x[__ldg(g_ssrc + j) * 32 + lane];
        float e = fmaf(p, xs, qxd); e = fmaxf(e, 0.2f * e); e = __expf(e);
        s += e; t = fmaf(e, xs, t);
    }

    g_s[n * 32 + lane] = s;
    float v = gw * t / s + __ldg(gatb);
    float xe = v > 0.f ? v : (__expf(v) - 1.f);
    g_xenc[n * 32 + lane] = xe;

    // fused classifier partial: accumulate xe * clfw[c][n] into block-local slog
    float c0 = __ldg(clfw + n);
    float c1 = __ldg(clfw + NN + n);
    float c2 = __ldg(clfw + 2 * NN + n);
    float c3 = __ldg(clfw + 3 * NN + n);
    atomicAdd(&slog[lane * 4 + 0], xe * c0);
    atomicAdd(&slog[lane * 4 + 1], xe * c1);
    atomicAdd(&slog[lane * 4 + 2], xe * c2);
    atomicAdd(&slog[lane * 4 + 3], xe * c3);
    __syncthreads();
    if (threadIdx.x < BB * 4) atomicAdd(&g_logits[threadIdx.x], slog[threadIdx.x]);
}

// ---------------------------------------------------------------- GCN pass + community epilogue + coalesced out
__global__ void k_gcn(const float* __restrict__ gatw, const float* __restrict__ asrc,
                      const float* __restrict__ adst,
                      const float* __restrict__ gcnw, const float* __restrict__ gcnb,
                      const float* __restrict__ lng, const float* __restrict__ lnb,
                      float* __restrict__ out) {
    __shared__ float sout[BB][25];
    int w8 = threadIdx.x >> 5;
    int n = blockIdx.x * 8 + w8;
    int lane = threadIdx.x & 31;
    float gw = __ldg(gatw);
    float p  = gw * __ldg(asrc);
    float q  = gw * __ldg(adst);

    float xd = g_x[n * 32 + lane];
    float qxd = q * xd;
    float ev = p * xd + qxd;
    ev = fmaxf(ev, 0.2f * ev);
    float ex = __expf(ev);
    float u = ex * g_xenc[n * 32 + lane];

    int beg = g_offs[n], end = g_offs[n + 1];
    int j = beg;
    for (; j < end && (j & 3); ++j) {
        int sj = __ldg(g_ssrc + j);
        float xs = g_x[sj * 32 + lane];
        float e = fmaf(p, xs, qxd); e = fmaxf(e, 0.2f * e); e = __expf(e);
        u = fmaf(e, g_xenc[sj * 32 + lane], u);
    }
    for (; j + 8 <= end; j += 8) {
        int4 iA = *reinterpret_cast<const int4*>(g_ssrc + j);
        int4 iB = *reinterpret_cast<const int4*>(g_ssrc + j + 4);
        int idx[8] = {iA.x, iA.y, iA.z, iA.w, iB.x, iB.y, iB.z, iB.w};
        float xv[8], hv[8];
#pragma unroll
        for (int r = 0; r < 8; ++r) xv[r] = g_x[idx[r] * 32 + lane];
#pragma unroll
        for (int r = 0; r < 8; ++r) hv[r] = g_xenc[idx[r] * 32 + lane];
#pragma unroll
        for (int r = 0; r < 8; ++r) {
            float e = fmaf(p, xv[r], qxd);
            e = fmaxf(e, 0.2f * e);
            e = __expf(e);
            u = fmaf(e, hv[r], u);
        }
    }
    for (; j < end; ++j) {
        int sj = __ldg(g_ssrc + j);
        float xs = g_x[sj * 32 + lane];
        float e = fmaf(p, xs, qxd); e = fmaxf(e, 0.2f * e); e = __expf(e);
        u = fmaf(e, g_xenc[sj * 32 + lane], u);
    }

    float y = u / g_s[n * 32 + lane];   // weighted degree == 1 -> norm == alpha

    float c0 = y * __ldg(gcnw + 0) + __ldg(gcnb + 0);
    float c1 = y * __ldg(gcnw + 1) + __ldg(gcnb + 1);
    float c2 = y * __ldg(gcnw + 2) + __ldg(gcnb + 2);
    c0 = fmaxf(c0, 0.01f * c0);
    c1 = fmaxf(c1, 0.01f * c1);
    c2 = fmaxf(c2, 0.01f * c2);
    float mu = (c0 + c1 + c2) * (1.f / 3.f);
    float d0 = c0 - mu, d1 = c1 - mu, d2 = c2 - mu;
    float var = (d0*d0 + d1*d1 + d2*d2) * (1.f / 3.f);
    float r = rsqrtf(var + 1e-5f);
    float v0 = d0 * r * __ldg(lng + 0) + __ldg(lnb + 0);
    float v1 = d1 * r * __ldg(lng + 1) + __ldg(lnb + 1);
    float v2 = d2 * r * __ldg(lng + 2) + __ldg(lnb + 2);
    float m = fmaxf(v0, fmaxf(v1, v2));
    float a0 = __expf(v0 - m), a1 = __expf(v1 - m), a2 = __expf(v2 - m);
    float inv = 1.f / (a0 + a1 + a2);

    sout[lane][w8 * 3 + 0] = a0 * inv;
    sout[lane][w8 * 3 + 1] = a1 * inv;
    sout[lane][w8 * 3 + 2] = a2 * inv;
    __syncthreads();

    int b = threadIdx.x >> 3, seg = threadIdx.x & 7;
    int n0 = blockIdx.x * 8;
    size_t base = 128 + ((size_t)b * NN + n0 + seg) * 3;
    out[base + 0] = sout[b][seg * 3 + 0];
    out[base + 1] = sout[b][seg * 3 + 1];
    out[base + 2] = sout[b][seg * 3 + 2];
}

// ---------------------------------------------------------------- final softmax; resets g_logits for next replay
__global__ void k_final(const float* __restrict__ clfb, float* __restrict__ out) {
    int b = threadIdx.x;
    if (b >= BB) return;
    float l0 = g_logits[b * 4 + 0] + __ldg(clfb + 0);
    float l1 = g_logits[b * 4 + 1] + __ldg(clfb + 1);
    float l2 = g_logits[b * 4 + 2] + __ldg(clfb + 2);
    float l3 = g_logits[b * 4 + 3] + __ldg(clfb + 3);
    g_logits[b * 4 + 0] = 0.f;
    g_logits[b * 4 + 1] = 0.f;
    g_logits[b * 4 + 2] = 0.f;
    g_logits[b * 4 + 3] = 0.f;
    float m = fmaxf(fmaxf(l0, l1), fmaxf(l2, l3));
    float e0 = __expf(l0 - m), e1 = __expf(l1 - m), e2 = __expf(l2 - m), e3 = __expf(l3 - m);
    float inv = 1.f / (e0 + e1 + e2 + e3);
    out[b * 4 + 0] = e0 * inv;
    out[b * 4 + 1] = e1 * inv;
    out[b * 4 + 2] = e2 * inv;
    out[b * 4 + 3] = e3 * inv;
}

extern "C" void kernel_launch(void* const* d_in, const int* in_sizes, int n_in,
                              void* d_out, int out_size) {
    const float* fd    = (const float*)d_in[0];
    const float* fc1w  = (const float*)d_in[1];
    const float* fc1b  = (const float*)d_in[2];
    const float* gatw  = (const float*)d_in[3];
    const float* asrc  = (const float*)d_in[4];
    const float* adst  = (const float*)d_in[5];
    const float* gatb  = (const float*)d_in[6];
    const float* gcnw  = (const float*)d_in[7];
    const float* gcnb  = (const float*)d_in[8];
    const float* lng   = (const float*)d_in[9];
    const float* lnb   = (const float*)d_in[10];
    const float* clfw  = (const float*)d_in[11];
    const float* clfb  = (const float*)d_in[12];
    const int*   ei    = (const int*)d_in[13];
    float* out = (float*)d_out;

    k_pre<<<FC1_BLOCKS + DEG_BLOCKS, 256>>>(fd, fc1w, fc1b, ei);
    k_scan<<<SCAN_BLOCKS, 256>>>();
    k_scatter<<<SCAT_BLOCKS, 256>>>(ei);
    k_gat<<<GCN_BLOCKS, 256>>>(gatw, asrc, adst, gatb, clfw);
    k_gcn<<<GCN_BLOCKS, 256>>>(gatw, asrc, adst, gcnw, gcnb, lng, lnb, out);
    k_final<<<1, 32>>>(clfb, out);
}

// round 15
// speedup vs baseline: 2.0069x; 1.0892x over previous
#include <cuda_runtime.h>
#include <cuda_bf16.h>
#include <cstdint>

#define NN 50000
#define BB 32
#define FF 200
#define EE 800000
#define NB (NN*BB)  // 1,600,000

#define FC1_BLOCKS 196     // 256 nodes per 256-thr block (4 nodes x 8 batches / thread)
#define DEG_BLOCKS 782     // ceil(EE/1024), 4 edges per thread
#define SS_BLOCKS 391      // scan+scatter fused; ceil(EE/2048) for 8 edges/thread
#define SCAN_BLOCKS 196    // ceil(NN/256)
#define GCN_BLOCKS 6250    // NN/8
#define LOG_BLOCKS 128

// Scratch
__device__ float g_x[NB];      // fc1 output, node-major [n][b]
__device__ float g_s[NB];      // softmax denominator per (n,b)
__device__ float g_xenc[NB];   // elu(gat out)
__device__ float g_logits[BB*4];   // starts 0; k_final resets after reading
__device__ int   g_cnt[NN];        // starts 0; scan phase resets after reading
__device__ int   g_bsum[SCAN_BLOCKS];
__device__ int   g_offs[NN+1]; // CSR offsets
__device__ int   g_rank[EE];   // rank of edge within its dst bucket
__device__ int   g_ssrc[EE];   // dst-sorted src indices
__device__ int   g_flagA;      // barriers (self-resetting each replay)
__device__ int   g_flagB;
__device__ int   g_flagC;

typedef unsigned long long ull;

#define PACK2(dst, s) asm("mov.b64 %0, {%1, %1};" : "=l"(dst) : "f"(s))
#define FMA2(acc, a, b) asm("fma.rn.f32x2 %0, %1, %2, %0;" : "+l"(acc) : "l"(a), "l"(b))
#define UNPACK2(lo, hi, v) asm("mov.b64 {%0, %1}, %2;" : "=f"(lo), "=f"(hi) : "l"(v))

// ---------------------------------------------------------------- fused: fc1 (f32x2, 4 nodes/thread) + degree histogram
__global__ void __launch_bounds__(256) k_pre(const float* __restrict__ fd, const float* __restrict__ w,
                      const float* __restrict__ bias, const int* __restrict__ ei) {
    if (blockIdx.x < FC1_BLOCKS) {
        // ---- fc1: 4 nodes x 8 batches per thread, packed f32x2 FMA
        __shared__ __align__(16) float fdT[FF * BB];  // [k][b], 25.6KB
        int tid = threadIdx.x;
        for (int i = tid; i < FF * BB; i += 256) {
            int b = i / FF, k = i % FF;
            fdT[k * BB + b] = fd[i];
        }
        __syncthreads();

        int lane = tid & 31, warp = tid >> 5;
        int nq = lane >> 2;       // 0..7
        int bq = lane & 3;        // 0..3 -> batches 8bq..8bq+7 (4 pairs)
        int node0 = (blockIdx.x * 8 + warp) * 32 + nq * 4;   // nodes node0..node0+3
        bool vv[4];
        const float4* wp[4];
#pragma unroll
        for (int r = 0; r < 4; ++r) {
            vv[r] = (node0 + r < NN);
            wp[r] = reinterpret_cast<const float4*>(w + (vv[r] ? (size_t)(node0 + r) * FF : 0));
        }

        ull acc[4][4];
#pragma unroll
        for (int r = 0; r < 4; ++r)
#pragma unroll
            for (int j = 0; j < 4; ++j) acc[r][j] = 0ull;

        const ull* fbase = reinterpret_cast<const ull*>(fdT) + bq * 4;  // 4 pairs (8 batches)

#pragma unroll 2
        for (int k4 = 0; k4 < FF / 4; ++k4) {
            float4 wr0 = __ldg(wp[0] + k4);
            float4 wr1 = __ldg(wp[1] + k4);
            float4 wr2 = __ldg(wp[2] + k4);
            float4 wr3 = __ldg(wp[3] + k4);
            float ws[4][4] = {{wr0.x, wr0.y, wr0.z, wr0.w},
                              {wr1.x, wr1.y, wr1.z, wr1.w},
                              {wr2.x, wr2.y, wr2.z, wr2.w},
                              {wr3.x, wr3.y, wr3.z, wr3.w}};
#pragma unroll
            for (int kk = 0; kk < 4; ++kk) {
                const ull* fp = fbase + (k4 * 4 + kk) * (BB / 2);
                ull f0 = fp[0], f1 = fp[1], f2 = fp[2], f3 = fp[3];
#pragma unroll
                for (int r = 0; r < 4; ++r) {
                    ull ww;
                    PACK2(ww, ws[r][kk]);
                    FMA2(acc[r][0], ww, f0);
                    FMA2(acc[r][1], ww, f1);
                    FMA2(acc[r][2], ww, f2);
                    FMA2(acc[r][3], ww, f3);
                }
            }
        }

#pragma unroll
        for (int r = 0; r < 4; ++r) {
            if (!vv[r]) continue;
            float b = __ldg(bias + node0 + r);
            float l0,h0,l1,h1,l2,h2,l3,h3;
            UNPACK2(l0,h0,acc[r][0]); UNPACK2(l1,h1,acc[r][1]);
            UNPACK2(l2,h2,acc[r][2]); UNPACK2(l3,h3,acc[r][3]);
            float4* gx = reinterpret_cast<float4*>(g_x + (size_t)(node0 + r) * 32 + bq * 8);
            gx[0] = make_float4(l0+b, h0+b, l1+b, h1+b);
            gx[1] = make_float4(l2+b, h2+b, l3+b, h3+b);
        }
    } else {
        // ---- degree histogram + per-edge rank, 4 edges/thread
        int e0 = ((blockIdx.x - FC1_BLOCKS) * 256 + threadIdx.x) * 4;
        if (e0 >= EE) return;
        int4 d4 = __ldg(reinterpret_cast<const int4*>(ei + EE) + (e0 >> 2));
        int r0 = atomicAdd(&g_cnt[d4.x], 1);
        int r1 = atomicAdd(&g_cnt[d4.y], 1);
        int r2 = atomicAdd(&g_cnt[d4.z], 1);
        int r3 = atomicAdd(&g_cnt[d4.w], 1);
        *reinterpret_cast<int4*>(g_rank + e0) = make_int4(r0, r1, r2, r3);
    }
}

// ---------------------------------------------------------------- fused scan + scatter (soft grid barriers, 391 co-resident blocks)
__global__ void __launch_bounds__(256) k_scanscat(const int* __restrict__ ei) {
    __shared__ int s2[256];
    __shared__ int sb[256];
    int t = threadIdx.x;
    int blk = blockIdx.x;
    int i = blk * 256 + t;
    int c = 0;
    int locInc = 0;

    // ---- phase 1: block-local inclusive scan of degree counts (first 196 blocks)
    if (blk < SCAN_BLOCKS) {
        c = (i < NN) ? g_cnt[i] : 0;
        s2[t] = c;
        __syncthreads();
#pragma unroll
        for (int off = 1; off < 256; off <<= 1) {
            int tmp = (t >= off) ? s2[t - off] : 0;
            __syncthreads();
            s2[t] += tmp;
            __syncthreads();
        }
        locInc = s2[t];
        if (t == 255) {
            g_bsum[blk] = s2[255];
            __threadfence();
            atomicAdd(&g_flagA, 1);
        }
    } else {
        if (t == 0) atomicAdd(&g_flagA, 1);
    }
    // barrier A: all 391 blocks
    if (t == 0) {
        while (*((volatile int*)&g_flagA) < SS_BLOCKS) { __nanosleep(64); }
    }
    __syncthreads();
    __threadfence();

    // ---- phase 2: offsets (first 196 blocks), then barrier B
    if (blk < SCAN_BLOCKS) {
        sb[t] = (t < SCAN_BLOCKS) ? *((volatile int*)&g_bsum[t]) : 0;
        __syncthreads();
#pragma unroll
        for (int off = 1; off < 256; off <<= 1) {
            int tmp = (t >= off) ? sb[t - off] : 0;
            __syncthreads();
            sb[t] += tmp;
            __syncthreads();
        }
        int boff = (blk == 0) ? 0 : sb[blk - 1];
        if (i < NN) {
            g_offs[i] = boff + (locInc - c);   // exclusive
            g_cnt[i] = 0;                       // restore invariant for next replay
        }
        if (blk == 0 && t == 0) g_offs[NN] = EE;
        __syncthreads();
        if (t == 0) { __threadfence(); atomicAdd(&g_flagB, 1); }
    } else {
        if (t == 0) atomicAdd(&g_flagB, 1);
    }
    // barrier B: all 391 blocks
    if (t == 0) {
        while (*((volatile int*)&g_flagB) < SS_BLOCKS) { __nanosleep(64); }
    }
    __syncthreads();
    __threadfence();

    // ---- phase 3: scatter, 8 edges/thread, atomic-free
    int e0 = (blk * 256 + t) * 8;
    if (e0 < EE) {
        int4 sA = __ldg(reinterpret_cast<const int4*>(ei) + (e0 >> 2));
        int4 sB = __ldg(reinterpret_cast<const int4*>(ei) + (e0 >> 2) + 1);
        int4 dA = __ldg(reinterpret_cast<const int4*>(ei + EE) + (e0 >> 2));
        int4 dB = __ldg(reinterpret_cast<const int4*>(ei + EE) + (e0 >> 2) + 1);
        int4 rA = *reinterpret_cast<const int4*>(g_rank + e0);
        int4 rB = *reinterpret_cast<const int4*>(g_rank + e0 + 4);
        g_ssrc[g_offs[dA.x] + rA.x] = sA.x;
        g_ssrc[g_offs[dA.y] + rA.y] = sA.y;
        g_ssrc[g_offs[dA.z] + rA.z] = sA.z;
        g_ssrc[g_offs[dA.w] + rA.w] = sA.w;
        g_ssrc[g_offs[dB.x] + rB.x] = sB.x;
        g_ssrc[g_offs[dB.y] + rB.y] = sB.y;
        g_ssrc[g_offs[dB.z] + rB.z] = sB.z;
        g_ssrc[g_offs[dB.w] + rB.w] = sB.w;
    }

    // ---- reset barrier flags (391st passer resets; all spinners already through)
    __syncthreads();
    if (t == 0) {
        int v = atomicAdd(&g_flagC, 1);
        if (v == SS_BLOCKS - 1) { g_flagA = 0; g_flagB = 0; g_flagC = 0; __threadfence(); }
    }
}

// ---------------------------------------------------------------- GAT pass: warp per dst node, lane = batch (lean)
__global__ void k_gat(const float* __restrict__ gatw, const float* __restrict__ asrc,
                      const float* __restrict__ adst, const float* __restrict__ gatb) {
    int n = blockIdx.x * 8 + (threadIdx.x >> 5);
    int lane = threadIdx.x & 31;
    float gw = __ldg(gatw);
    float p  = gw * __ldg(asrc);
    float q  = gw * __ldg(adst);

    float xd = g_x[n * 32 + lane];
    float qxd = q * xd;
    float ev = p * xd + qxd;
    ev = fmaxf(ev, 0.2f * ev);
    float ex = __expf(ev);
    float s = ex, t = ex * xd;

    int beg = g_offs[n], end = g_offs[n + 1];
    int j = beg;
    for (; j < end && (j & 3); ++j) {
        float xs = g_x[__ldg(g_ssrc + j) * 32 + lane];
        float e = fmaf(p, xs, qxd); e = fmaxf(e, 0.2f * e); e = __expf(e);
        s += e; t = fmaf(e, xs, t);
    }
    for (; j + 8 <= end; j += 8) {
        int4 iA = *reinterpret_cast<const int4*>(g_ssrc + j);
        int4 iB = *reinterpret_cast<const int4*>(g_ssrc + j + 4);
        int idx[8] = {iA.x, iA.y, iA.z, iA.w, iB.x, iB.y, iB.z, iB.w};
        float xv[8];
#pragma unroll
        for (int r = 0; r < 8; ++r) xv[r] = g_x[idx[r] * 32 + lane];
#pragma unroll
        for (int r = 0; r < 8; ++r) {
            float e = fmaf(p, xv[r], qxd);
            e = fmaxf(e, 0.2f * e);
            e = __expf(e);
            s += e; t = fmaf(e, xv[r], t);
        }
    }
    for (; j < end; ++j) {
        float xs = g_x[__ldg(g_ssrc + j) * 32 + lane];
        float e = fmaf(p, xs, qxd); e = fmaxf(e, 0.2f * e); e = __expf(e);
        s += e; t = fmaf(e, xs, t);
    }

    g_s[n * 32 + lane] = s;
    float v = gw * t / s + __ldg(gatb);
    g_xenc[n * 32 + lane] = v > 0.f ? v : (__expf(v) - 1.f);
}

// ---------------------------------------------------------------- fused: classifier logits (blocks [0,LOG)) + GCN pass
__global__ void k_gcnlog(const float* __restrict__ gatw, const float* __restrict__ asrc,
                         const float* __restrict__ adst,
                         const float* __restrict__ gcnw, const float* __restrict__ gcnb,
                         const float* __restrict__ lng, const float* __restrict__ lnb,
                         const float* __restrict__ clfw,
                         float* __restrict__ out) {
    if (blockIdx.x < LOG_BLOCKS) {
        // ---- classifier partial reduction
        int wid = (blockIdx.x * 256 + threadIdx.x) >> 5;
        int lane = threadIdx.x & 31;
        const int W = LOG_BLOCKS * 8;
        float a0 = 0.f, a1 = 0.f, a2 = 0.f, a3 = 0.f;
        for (int n = wid; n < NN; n += W) {
            float v = g_xenc[n * 32 + lane];
            a0 = fmaf(v, __ldg(clfw + n),          a0);
            a1 = fmaf(v, __ldg(clfw + NN + n),     a1);
            a2 = fmaf(v, __ldg(clfw + 2 * NN + n), a2);
            a3 = fmaf(v, __ldg(clfw + 3 * NN + n), a3);
        }
        atomicAdd(&g_logits[lane * 4 + 0], a0);
        atomicAdd(&g_logits[lane * 4 + 1], a1);
        atomicAdd(&g_logits[lane * 4 + 2], a2);
        atomicAdd(&g_logits[lane * 4 + 3], a3);
        return;
    }

    // ---- GCN pass + community epilogue + coalesced out
    __shared__ float sout[BB][25];
    int blk = blockIdx.x - LOG_BLOCKS;
    int w8 = threadIdx.x >> 5;
    int n = blk * 8 + w8;
    int lane = threadIdx.x & 31;
    float gw = __ldg(gatw);
    float p  = gw * __ldg(asrc);
    float q  = gw * __ldg(adst);

    float xd = g_x[n * 32 + lane];
    float qxd = q * xd;
    float ev = p * xd + qxd;
    ev = fmaxf(ev, 0.2f * ev);
    float ex = __expf(ev);
    float u = ex * g_xenc[n * 32 + lane];

    int beg = g_offs[n], end = g_offs[n + 1];
    int j = beg;
    for (; j < end && (j & 3); ++j) {
        int sj = __ldg(g_ssrc + j);
        float xs = g_x[sj * 32 + lane];
        float e = fmaf(p, xs, qxd); e = fmaxf(e, 0.2f * e); e = __expf(e);
        u = fmaf(e, g_xenc[sj * 32 + lane], u);
    }
    for (; j + 8 <= end; j += 8) {
        int4 iA = *reinterpret_cast<const int4*>(g_ssrc + j);
        int4 iB = *reinterpret_cast<const int4*>(g_ssrc + j + 4);
        int idx[8] = {iA.x, iA.y, iA.z, iA.w, iB.x, iB.y, iB.z, iB.w};
        float xv[8], hv[8];
#pragma unroll
        for (int r = 0; r < 8; ++r) xv[r] = g_x[idx[r] * 32 + lane];
#pragma unroll
        for (int r = 0; r < 8; ++r) hv[r] = g_xenc[idx[r] * 32 + lane];
#pragma unroll
        for (int r = 0; r < 8; ++r) {
            float e = fmaf(p, xv[r], qxd);
            e = fmaxf(e, 0.2f * e);
            e = __expf(e);
            u = fmaf(e, hv[r], u);
        }
    }
    for (; j < end; ++j) {
        int sj = __ldg(g_ssrc + j);
        float xs = g_x[sj * 32 + lane];
        float e = fmaf(p, xs, qxd); e = fmaxf(e, 0.2f * e); e = __expf(e);
        u = fmaf(e, g_xenc[sj * 32 + lane], u);
    }

    float y = u / g_s[n * 32 + lane];   // weighted degree == 1 -> norm == alpha

    float c0 = y * __ldg(gcnw + 0) + __ldg(gcnb + 0);
    float c1 = y * __ldg(gcnw + 1) + __ldg(gcnb + 1);
    float c2 = y * __ldg(gcnw + 2) + __ldg(gcnb + 2);
    c0 = fmaxf(c0, 0.01f * c0);
    c1 = fmaxf(c1, 0.01f * c1);
    c2 = fmaxf(c2, 0.01f * c2);
    float mu = (c0 + c1 + c2) * (1.f / 3.f);
    float d0 = c0 - mu, d1 = c1 - mu, d2 = c2 - mu;
    float var = (d0*d0 + d1*d1 + d2*d2) * (1.f / 3.f);
    float r = rsqrtf(var + 1e-5f);
    float v0 = d0 * r * __ldg(lng + 0) + __ldg(lnb + 0);
    float v1 = d1 * r * __ldg(lng + 1) + __ldg(lnb + 1);
    float v2 = d2 * r * __ldg(lng + 2) + __ldg(lnb + 2);
    float m = fmaxf(v0, fmaxf(v1, v2));
    float a0 = __expf(v0 - m), a1 = __expf(v1 - m), a2 = __expf(v2 - m);
    float inv = 1.f / (a0 + a1 + a2);

    sout[lane][w8 * 3 + 0] = a0 * inv;
    sout[lane][w8 * 3 + 1] = a1 * inv;
    sout[lane][w8 * 3 + 2] = a2 * inv;
    __syncthreads();

    int b = threadIdx.x >> 3, seg = threadIdx.x & 7;
    int n0 = blk * 8;
    size_t base = 128 + ((size_t)b * NN + n0 + seg) * 3;
    out[base + 0] = sout[b][seg * 3 + 0];
    out[base + 1] = sout[b][seg * 3 + 1];
    out[base + 2] = sout[b][seg * 3 + 2];
}

// ---------------------------------------------------------------- final softmax; resets g_logits for next replay
__global__ void k_final(const float* __restrict__ clfb, float* __restrict__ out) {
    int b = threadIdx.x;
    if (b >= BB) return;
    float l0 = g_logits[b * 4 + 0] + __ldg(clfb + 0);
    float l1 = g_logits[b * 4 + 1] + __ldg(clfb + 1);
    float l2 = g_logits[b * 4 + 2] + __ldg(clfb + 2);
    float l3 = g_logits[b * 4 + 3] + __ldg(clfb + 3);
    g_logits[b * 4 + 0] = 0.f;
    g_logits[b * 4 + 1] = 0.f;
    g_logits[b * 4 + 2] = 0.f;
    g_logits[b * 4 + 3] = 0.f;
    float m = fmaxf(fmaxf(l0, l1), fmaxf(l2, l3));
    float e0 = __expf(l0 - m), e1 = __expf(l1 - m), e2 = __expf(l2 - m), e3 = __expf(l3 - m);
    float inv = 1.f / (e0 + e1 + e2 + e3);
    out[b * 4 + 0] = e0 * inv;
    out[b * 4 + 1] = e1 * inv;
    out[b * 4 + 2] = e2 * inv;
    out[b * 4 + 3] = e3 * inv;
}

extern "C" void kernel_launch(void* const* d_in, const int* in_sizes, int n_in,
                              void* d_out, int out_size) {
    const float* fd    = (const float*)d_in[0];
    const float* fc1w  = (const float*)d_in[1];
    const float* fc1b  = (const float*)d_in[2];
    const float* gatw  = (const float*)d_in[3];
    const float* asrc  = (const float*)d_in[4];
    const float* adst  = (const float*)d_in[5];
    const float* gatb  = (const float*)d_in[6];
    const float* gcnw  = (const float*)d_in[7];
    const float* gcnb  = (const float*)d_in[8];
    const float* lng   = (const float*)d_in[9];
    const float* lnb   = (const float*)d_in[10];
    const float* clfw  = (const float*)d_in[11];
    const float* clfb  = (const float*)d_in[12];
    const int*   ei    = (const int*)d_in[13];
    float* out = (float*)d_out;

    k_pre<<<FC1_BLOCKS + DEG_BLOCKS, 256>>>(fd, fc1w, fc1b, ei);
    k_scanscat<<<SS_BLOCKS, 256>>>(ei);
    k_gat<<<GCN_BLOCKS, 256>>>(gatw, asrc, adst, gatb);
    k_gcnlog<<<LOG_BLOCKS + GCN_BLOCKS, 256>>>(gatw, asrc, adst, gcnw, gcnb, lng, lnb, clfw, out);
    k_final<<<1, 32>>>(clfb, out);
}